// round 12
// baseline (speedup 1.0000x reference)
#include <cuda_runtime.h>
#include <math.h>
#include <stdint.h>

#define SEQ 12
#define MAX_N 100000

// Inter-layer scratch + work-stealing counters (allocation-free)
__device__ float g_h1[MAX_N * 64];
__device__ float g_h2[MAX_N * 64];
__device__ unsigned int g_ctr[4];

// ---- packed f32x2 helpers (Blackwell, family-generic PTX) ----
__device__ __forceinline__ unsigned long long dup_f32(float a) {
    unsigned long long r;
    asm("mov.b64 %0, {%1, %1};" : "=l"(r) : "f"(a));
    return r;
}
__device__ __forceinline__ void ffma2(unsigned long long& d, unsigned long long a,
                                      unsigned long long b) {
    asm("fma.rn.f32x2 %0, %1, %2, %0;" : "+l"(d) : "l"(a), "l"(b));
}
__device__ __forceinline__ float2 unpack2(unsigned long long v) {
    float2 r;
    asm("mov.b64 {%0, %1}, %2;" : "=f"(r.x), "=f"(r.y) : "l"(v));
    return r;
}

// ---- cp.async helpers (.cg bypasses L1 -> keeps L1D free for W) ----
__device__ __forceinline__ void cp16(void* smem_dst, const void* gsrc) {
    unsigned sa = (unsigned)__cvta_generic_to_shared(smem_dst);
    asm volatile("cp.async.cg.shared.global [%0], [%1], 16;" ::"r"(sa), "l"(gsrc));
}
__device__ __forceinline__ void cp_commit() {
    asm volatile("cp.async.commit_group;" ::: "memory");
}
__device__ __forceinline__ void cp_wait_all() {
    asm volatile("cp.async.wait_group 0;" ::: "memory");
}

__global__ void zero_ctr() {
    if (threadIdx.x < 4) g_ctr[threadIdx.x] = 0u;
}

// Persistent spiral-conv layer with work-stealing tiles.
// Thread micro-tile: NPT=8 nodes (strided by TY) x GRAN*4 outs, packed f32x2.
// A: gathered via double-buffered cp.async into smem (conflict-free layout).
// B (W slice): read directly from global via __ldg (L1-resident, broadcast).
template <int C_IN, int C_OUT, int GRAN, bool ACT>
__global__ __launch_bounds__(128, 4) void spiral_pers(
    const float* __restrict__ h_in, const int* __restrict__ idx,
    const float* __restrict__ W, const float* __restrict__ bias,
    float* __restrict__ h_out, int n_nodes, int ntiles, int ctr_id) {
    constexpr int THREADS = 128;
    constexpr int NPT = 8;                  // nodes per thread
    constexpr int TX = C_OUT / (4 * GRAN);  // threads along outs (8)
    constexpr int TY = THREADS / TX;        // 16 thread rows
    constexpr int TILE_N = NPT * TY;        // 128 nodes per tile
    constexpr int LDA = C_IN + 4;           // bank-conflict-free A stride
    constexpr int TPR = C_IN / 4;           // 16B chunks per A row
    constexpr int RPP = THREADS / TPR;      // rows gathered per pass
    constexpr int ABUF = TILE_N * LDA;      // floats per A buffer

    extern __shared__ float smem[];
    float* sA = smem;                        // [2][ABUF]
    int* sT = (int*)(smem + 2 * ABUF);       // broadcast tile id

    const int tid = threadIdx.x;
    const int tx = tid % TX, ty = tid / TX;
    const int rr = tid / TPR, c4 = tid % TPR;
    unsigned int* ctr = &g_ctr[ctr_id];

    auto issue = [&](int t, int s, int buf) {
        float* A = sA + buf * ABUF;
        const int nb = t * TILE_N;
#pragma unroll
        for (int r0 = 0; r0 < TILE_N; r0 += RPP) {
            const int r = r0 + rr;
            const int node = nb + r;
            const int g = (node < n_nodes) ? __ldg(&idx[node * SEQ + s]) : 0;
            cp16(&A[r * LDA + c4 * 4], h_in + (size_t)g * C_IN + c4 * 4);
        }
        cp_commit();
    };

    if (tid == 0) sT[0] = (int)atomicAdd(ctr, 1u);
    __syncthreads();
    int t = sT[0];

    while (t < ntiles) {
        issue(t, 0, 0);

        unsigned long long acc[NPT][2 * GRAN];
#pragma unroll
        for (int i = 0; i < NPT; ++i)
#pragma unroll
            for (int p = 0; p < 2 * GRAN; ++p) acc[i][p] = 0ull;

#pragma unroll 1
        for (int s = 0; s < SEQ; ++s) {
            cp_wait_all();
            __syncthreads();
            if (s + 1 < SEQ) issue(t, s + 1, (s + 1) & 1);

            const float* A = sA + (s & 1) * ABUF;
            const float* Ws = W + (size_t)s * C_IN * C_OUT;

#pragma unroll 2
            for (int k0 = 0; k0 < C_IN; k0 += 4) {
                float4 a4[NPT];
#pragma unroll
                for (int i = 0; i < NPT; ++i)
                    a4[i] = *reinterpret_cast<const float4*>(
                        &A[(i * TY + ty) * LDA + k0]);
#pragma unroll
                for (int kk = 0; kk < 4; ++kk) {
                    const float* brow = Ws + (k0 + kk) * C_OUT;
                    ulonglong2 b[GRAN];
#pragma unroll
                    for (int p = 0; p < GRAN; ++p)
                        b[p] = *reinterpret_cast<const ulonglong2*>(
                            brow + (tx + p * TX) * 4);
#pragma unroll
                    for (int i = 0; i < NPT; ++i) {
                        const float av = (kk == 0)   ? a4[i].x
                                         : (kk == 1) ? a4[i].y
                                         : (kk == 2) ? a4[i].z
                                                     : a4[i].w;
                        const unsigned long long a2 = dup_f32(av);
#pragma unroll
                        for (int p = 0; p < GRAN; ++p) {
                            ffma2(acc[i][2 * p], a2, b[p].x);
                            ffma2(acc[i][2 * p + 1], a2, b[p].y);
                        }
                    }
                }
            }
        }

        // Fetch next tile (overlaps epilogue), then write out.
        if (tid == 0) sT[0] = (int)atomicAdd(ctr, 1u);

#pragma unroll
        for (int i = 0; i < NPT; ++i) {
            const int n = t * TILE_N + i * TY + ty;
            if (n < n_nodes) {
#pragma unroll
                for (int p = 0; p < GRAN; ++p) {
                    const int col = (tx + p * TX) * 4;
                    const float2 u0 = unpack2(acc[i][2 * p]);
                    const float2 u1 = unpack2(acc[i][2 * p + 1]);
                    float o[4] = {u0.x, u0.y, u1.x, u1.y};
#pragma unroll
                    for (int j = 0; j < 4; ++j) {
                        float v = o[j] + __ldg(&bias[col + j]);
                        if (ACT) v = (v > 0.0f) ? v : expm1f(v);
                        o[j] = v;
                    }
                    *reinterpret_cast<float4*>(h_out + (size_t)n * C_OUT + col) =
                        make_float4(o[0], o[1], o[2], o[3]);
                }
            }
        }
        __syncthreads();
        t = sT[0];
    }
}

template <int C_IN, int C_OUT>
constexpr int smem_sz() {
    return 2 * 128 * (C_IN + 4) * 4 + 16;
}

extern "C" void kernel_launch(void* const* d_in, const int* in_sizes, int n_in,
                              void* d_out, int out_size) {
    const float* x = (const float*)d_in[0];    // [N,32]
    const int* idx = (const int*)d_in[1];      // [N,12]
    const float* W0 = (const float*)d_in[2];   // [384,64]
    const float* b0 = (const float*)d_in[3];
    const float* W1 = (const float*)d_in[4];   // [768,64]
    const float* b1 = (const float*)d_in[5];
    const float* W2 = (const float*)d_in[6];   // [768,32]
    const float* b2 = (const float*)d_in[7];
    float* out = (float*)d_out;                // [N,32]

    const int n = in_sizes[0] / 32;
    const int ntiles = (n + 127) / 128;

    float *h1, *h2;
    cudaGetSymbolAddress((void**)&h1, g_h1);
    cudaGetSymbolAddress((void**)&h2, g_h2);

    constexpr int S0 = smem_sz<32, 64>();   // ~36.9 KB -> 4 CTAs/SM
    constexpr int S1 = smem_sz<64, 64>();   // ~68 KB   -> 3 CTAs/SM
    constexpr int S2 = smem_sz<64, 32>();   // ~68 KB   -> 3 CTAs/SM

    cudaFuncSetAttribute(spiral_pers<32, 64, 2, true>,
                         cudaFuncAttributeMaxDynamicSharedMemorySize, S0);
    cudaFuncSetAttribute(spiral_pers<64, 64, 2, true>,
                         cudaFuncAttributeMaxDynamicSharedMemorySize, S1);
    cudaFuncSetAttribute(spiral_pers<64, 32, 1, false>,
                         cudaFuncAttributeMaxDynamicSharedMemorySize, S2);

    zero_ctr<<<1, 32>>>();

    const int G0 = 148 * 4;  // resident capacity, work-stealing fills evenly
    const int G1 = 148 * 3;
    const int G2 = 148 * 3;

    spiral_pers<32, 64, 2, true><<<G0, 128, S0>>>(x, idx, W0, b0, h1, n, ntiles, 0);
    spiral_pers<64, 64, 2, true><<<G1, 128, S1>>>(h1, idx, W1, b1, h2, n, ntiles, 1);
    spiral_pers<64, 32, 1, false><<<G2, 128, S2>>>(h2, idx, W2, b2, out, n, ntiles, 2);
}

// round 13
// speedup vs baseline: 1.5765x; 1.5765x over previous
#include <cuda_runtime.h>
#include <cuda_bf16.h>
#include <math.h>
#include <stdint.h>

#define SEQ 12
#define MAX_N 100000

// Inter-layer scratch + prepped bf16 hi/lo W images (allocation-free)
__device__ float g_h1[MAX_N * 64];
__device__ float g_h2[MAX_N * 64];
// W_T images: per s: [hi: C_OUT x PADK][lo: C_OUT x PADK] bf16, PADK = C_IN+8
__device__ __align__(16) unsigned short g_w0b[SEQ * 2 * 64 * 40];
__device__ __align__(16) unsigned short g_w1b[SEQ * 2 * 64 * 72];
__device__ __align__(16) unsigned short g_w2b[SEQ * 2 * 32 * 72];

// ---- cp.async ----
__device__ __forceinline__ void cp16(uint32_t smem_dst, const void* gsrc) {
    asm volatile("cp.async.cg.shared.global [%0], [%1], 16;" ::"r"(smem_dst),
                 "l"(gsrc));
}
__device__ __forceinline__ void cp_commit() {
    asm volatile("cp.async.commit_group;" ::: "memory");
}
__device__ __forceinline__ void cp_wait_all() {
    asm volatile("cp.async.wait_group 0;" ::: "memory");
}

// ---- tensor-core primitives (sm_80 baseline -> valid on sm_103 family) ----
__device__ __forceinline__ void ldsm4(uint32_t* r, uint32_t a) {
    asm volatile("ldmatrix.sync.aligned.m8n8.x4.shared.b16 {%0,%1,%2,%3},[%4];"
                 : "=r"(r[0]), "=r"(r[1]), "=r"(r[2]), "=r"(r[3])
                 : "r"(a));
}
__device__ __forceinline__ void mma16(float* c, const uint32_t* a, uint32_t b0,
                                      uint32_t b1) {
    asm volatile(
        "mma.sync.aligned.m16n8k16.row.col.f32.bf16.bf16.f32 "
        "{%0,%1,%2,%3},{%4,%5,%6,%7},{%8,%9},{%0,%1,%2,%3};"
        : "+f"(c[0]), "+f"(c[1]), "+f"(c[2]), "+f"(c[3])
        : "r"(a[0]), "r"(a[1]), "r"(a[2]), "r"(a[3]), "r"(b0), "r"(b1));
}

// split x,y -> packed bf16 hi pair + lo pair (memory order: low 16 bits first)
__device__ __forceinline__ void split2(float x, float y, uint32_t& hi,
                                       uint32_t& lo) {
    __nv_bfloat16 hx = __float2bfloat16(x), hy = __float2bfloat16(y);
    float rx = x - __bfloat162float(hx), ry = y - __bfloat162float(hy);
    __nv_bfloat16 lx = __float2bfloat16(rx), ly = __float2bfloat16(ry);
    hi = ((uint32_t)__bfloat16_as_ushort(hy) << 16) | __bfloat16_as_ushort(hx);
    lo = ((uint32_t)__bfloat16_as_ushort(ly) << 16) | __bfloat16_as_ushort(lx);
}

// ---- prep: W[(s*C_IN+k)*C_OUT+n] -> W_T hi/lo bf16 images [s][comp][n][PADK]
template <int C_IN, int C_OUT>
__device__ void prep1(const float* __restrict__ W, unsigned short* __restrict__ img,
                      int e) {
    constexpr int PADK = C_IN + 8;
    const int per_s = C_IN * C_OUT;
    const int s = e / per_s, r = e % per_s;
    const int k = r / C_OUT, n = r % C_OUT;
    const float v = W[e];
    __nv_bfloat16 h = __float2bfloat16(v);
    __nv_bfloat16 l = __float2bfloat16(v - __bfloat162float(h));
    img[((size_t)(s * 2 + 0) * C_OUT + n) * PADK + k] = __bfloat16_as_ushort(h);
    img[((size_t)(s * 2 + 1) * C_OUT + n) * PADK + k] = __bfloat16_as_ushort(l);
}

__global__ void prep_kernel(const float* W0, const float* W1, const float* W2) {
    const int t = blockIdx.x * blockDim.x + threadIdx.x;
    const int n0 = SEQ * 32 * 64, n1 = SEQ * 64 * 64, n2 = SEQ * 64 * 32;
    if (t < n0) prep1<32, 64>(W0, g_w0b, t);
    const int t1 = t - n0;
    if (t1 >= 0 && t1 < n1) prep1<64, 64>(W1, g_w1b, t1);
    const int t2 = t1 - n1;
    if (t2 >= 0 && t2 < n2) prep1<64, 32>(W2, g_w2b, t2);
}

// ---- layer kernel: gather -> bf16 split -> 3-product m16n8k16 mma ----
template <int C_IN, int C_OUT, bool ACT>
__global__ __launch_bounds__(256) void spiral_mma(
    const float* __restrict__ h_in, const int* __restrict__ idx,
    const unsigned short* __restrict__ Bimg, const float* __restrict__ bias,
    float* __restrict__ h_out, int n_nodes) {
    constexpr int THREADS = 256, TILE_N = 128;
    constexpr int PADK = C_IN + 8;
    constexpr int ROWB = PADK * 2;            // bytes per smem row
    constexpr int ATILE = TILE_N * ROWB;      // bytes per A component
    constexpr int BTILE = C_OUT * ROWB;       // bytes per B component
    constexpr int NT = C_OUT / 8;             // n8 tiles
    constexpr int KS = C_IN / 16;             // k16 steps per neighbor
    constexpr int FPT = TILE_N * C_IN / THREADS;  // floats gathered per thread
    constexpr int V4 = FPT / 4;
    constexpr int TPR = C_IN / FPT;           // threads per gathered row (2)

    extern __shared__ char smem[];
    uint32_t sb;
    asm("{ .reg .u64 t; cvta.to.shared.u64 t, %1; cvt.u32.u64 %0, t; }"
        : "=r"(sb) : "l"(smem));
    char* Abase = smem;                  // [2 buf][2 comp][ATILE]
    const uint32_t sbB = sb + 4 * ATILE; // [2 buf][2*BTILE]

    const int tid = threadIdx.x, wid = tid >> 5, lane = tid & 31;
    const int g = lane >> 2, q = lane & 3;
    const int mbase = wid * 16;
    const int nb = blockIdx.x * TILE_N;

    // gather mapping: 2 threads per row
    const int grow = tid / TPR;
    const int goff = (tid % TPR) * FPT;

    // ldmatrix address offsets (within a component tile)
    const uint32_t aOff =
        (uint32_t)(mbase + (lane & 7) + ((lane >> 3) & 1) * 8) * ROWB +
        ((lane >> 4) & 1) * 16;
    const uint32_t bOff =
        (uint32_t)((lane & 7) + ((lane >> 4) & 1) * 8) * ROWB +
        ((lane >> 3) & 1) * 16;

    auto issueB = [&](int s, int buf) {
        const char* src = (const char*)(Bimg + (size_t)s * 2 * C_OUT * PADK);
        const uint32_t dst = sbB + buf * 2 * BTILE;
        constexpr int CH = 2 * BTILE / 16;
#pragma unroll
        for (int i = tid; i < CH; i += THREADS) cp16(dst + i * 16, src + i * 16);
        cp_commit();
    };

    float4 G[V4];
    auto loadA = [&](int s) {
        const int node = nb + grow;
        const int gi = (node < n_nodes) ? __ldg(&idx[node * SEQ + s]) : 0;
        const float4* src =
            reinterpret_cast<const float4*>(h_in + (size_t)gi * C_IN + goff);
#pragma unroll
        for (int j = 0; j < V4; ++j) G[j] = __ldg(src + j);
    };
    auto storeA = [&](int buf) {
        char* Ah = Abase + buf * 2 * ATILE;
        char* Al = Ah + ATILE;
#pragma unroll
        for (int j = 0; j < V4; ++j) {
            const float4 v = G[j];
            uint32_t h01, l01, h23, l23;
            split2(v.x, v.y, h01, l01);
            split2(v.z, v.w, h23, l23);
            const int off = grow * ROWB + (goff + 4 * j) * 2;
            *reinterpret_cast<uint2*>(Ah + off) = make_uint2(h01, h23);
            *reinterpret_cast<uint2*>(Al + off) = make_uint2(l01, l23);
        }
    };

    // preload bias pairs
    float2 br[NT];
#pragma unroll
    for (int nt = 0; nt < NT; ++nt) {
        const int c = nt * 8 + 2 * q;
        br[nt] = make_float2(__ldg(&bias[c]), __ldg(&bias[c + 1]));
    }

    issueB(0, 0);
    loadA(0);
    storeA(0);
    loadA(1);

    float acc[NT][4];
#pragma unroll
    for (int nt = 0; nt < NT; ++nt)
#pragma unroll
        for (int j = 0; j < 4; ++j) acc[nt][j] = 0.0f;

#pragma unroll 1
    for (int s = 0; s < SEQ; ++s) {
        const int buf = s & 1;
        cp_wait_all();
        __syncthreads();
        if (s + 1 < SEQ) issueB(s + 1, buf ^ 1);

        const uint32_t Ah = sb + buf * 2 * ATILE;
        const uint32_t Al = Ah + ATILE;
        const uint32_t Bh = sbB + buf * 2 * BTILE;
        const uint32_t Bl = Bh + BTILE;

#pragma unroll
        for (int k = 0; k < KS; ++k) {
            uint32_t ah[4], al[4];
            ldsm4(ah, Ah + aOff + k * 32);
            ldsm4(al, Al + aOff + k * 32);
#pragma unroll
            for (int j = 0; j < NT / 2; ++j) {
                uint32_t bh[4], bl[4];
                const uint32_t bo = bOff + j * 16 * ROWB + k * 32;
                ldsm4(bh, Bh + bo);
                ldsm4(bl, Bl + bo);
                mma16(acc[2 * j], ah, bh[0], bh[1]);
                mma16(acc[2 * j], al, bh[0], bh[1]);
                mma16(acc[2 * j], ah, bl[0], bl[1]);
                mma16(acc[2 * j + 1], ah, bh[2], bh[3]);
                mma16(acc[2 * j + 1], al, bh[2], bh[3]);
                mma16(acc[2 * j + 1], ah, bl[2], bl[3]);
            }
        }

        if (s + 1 < SEQ) {
            storeA(buf ^ 1);           // G holds A(s+1)
            if (s + 2 < SEQ) loadA(s + 2);
        }
    }

    // epilogue: bias + optional ELU, 8B stores
    const int r0 = nb + mbase + g;
    const int r1 = r0 + 8;
#pragma unroll
    for (int nt = 0; nt < NT; ++nt) {
        const int c = nt * 8 + 2 * q;
        float v0 = acc[nt][0] + br[nt].x;
        float v1 = acc[nt][1] + br[nt].y;
        float v2 = acc[nt][2] + br[nt].x;
        float v3 = acc[nt][3] + br[nt].y;
        if (ACT) {
            v0 = (v0 > 0.0f) ? v0 : expm1f(v0);
            v1 = (v1 > 0.0f) ? v1 : expm1f(v1);
            v2 = (v2 > 0.0f) ? v2 : expm1f(v2);
            v3 = (v3 > 0.0f) ? v3 : expm1f(v3);
        }
        if (r0 < n_nodes)
            *reinterpret_cast<float2*>(h_out + (size_t)r0 * C_OUT + c) =
                make_float2(v0, v1);
        if (r1 < n_nodes)
            *reinterpret_cast<float2*>(h_out + (size_t)r1 * C_OUT + c) =
                make_float2(v2, v3);
    }
}

template <int C_IN, int C_OUT>
constexpr int smem_sz() {
    return 4 * 128 * (C_IN + 8) * 2 + 4 * C_OUT * (C_IN + 8) * 2;
}

extern "C" void kernel_launch(void* const* d_in, const int* in_sizes, int n_in,
                              void* d_out, int out_size) {
    const float* x = (const float*)d_in[0];    // [N,32]
    const int* idx = (const int*)d_in[1];      // [N,12]
    const float* W0 = (const float*)d_in[2];
    const float* b0 = (const float*)d_in[3];
    const float* W1 = (const float*)d_in[4];
    const float* b1 = (const float*)d_in[5];
    const float* W2 = (const float*)d_in[6];
    const float* b2 = (const float*)d_in[7];
    float* out = (float*)d_out;

    const int n = in_sizes[0] / 32;
    const int grid = (n + 127) / 128;

    float *h1, *h2;
    unsigned short *w0b, *w1b, *w2b;
    cudaGetSymbolAddress((void**)&h1, g_h1);
    cudaGetSymbolAddress((void**)&h2, g_h2);
    cudaGetSymbolAddress((void**)&w0b, g_w0b);
    cudaGetSymbolAddress((void**)&w1b, g_w1b);
    cudaGetSymbolAddress((void**)&w2b, g_w2b);

    prep_kernel<<<(SEQ * (32 * 64 + 64 * 64 + 64 * 32) + 255) / 256, 256>>>(
        W0, W1, W2);

    constexpr int S0 = smem_sz<32, 64>();   // 61.4 KB -> 3 CTAs/SM
    constexpr int S1 = smem_sz<64, 64>();   // 110.6 KB -> 2 CTAs/SM
    constexpr int S2 = smem_sz<64, 32>();   // 92.2 KB -> 2 CTAs/SM
    cudaFuncSetAttribute(spiral_mma<32, 64, true>,
                         cudaFuncAttributeMaxDynamicSharedMemorySize, S0);
    cudaFuncSetAttribute(spiral_mma<64, 64, true>,
                         cudaFuncAttributeMaxDynamicSharedMemorySize, S1);
    cudaFuncSetAttribute(spiral_mma<64, 32, false>,
                         cudaFuncAttributeMaxDynamicSharedMemorySize, S2);

    spiral_mma<32, 64, true><<<grid, 256, S0>>>(x, idx, w0b, b0, h1, n);
    spiral_mma<64, 64, true><<<grid, 256, S1>>>(h1, idx, w1b, b1, h2, n);
    spiral_mma<64, 32, false><<<grid, 256, S2>>>(h2, idx, w2b, b2, out, n);
}

// round 17
// speedup vs baseline: 1.6163x; 1.0252x over previous
#include <cuda_runtime.h>
#include <cuda_bf16.h>
#include <math.h>
#include <stdint.h>

#define SEQ 12
#define MAX_N 100000

// Inter-layer scratch + prepped bf16 hi/lo W images (allocation-free)
__device__ float g_h1[MAX_N * 64];
__device__ float g_h2[MAX_N * 64];
// W_T images: per s: [hi: C_OUT x PADK][lo: C_OUT x PADK] bf16, PADK = C_IN+8
__device__ __align__(16) unsigned short g_w0b[SEQ * 2 * 64 * 40];
__device__ __align__(16) unsigned short g_w1b[SEQ * 2 * 64 * 72];
__device__ __align__(16) unsigned short g_w2b[SEQ * 2 * 32 * 72];

// ---- cp.async ----
__device__ __forceinline__ void cp16(uint32_t smem_dst, const void* gsrc) {
    asm volatile("cp.async.cg.shared.global [%0], [%1], 16;" ::"r"(smem_dst),
                 "l"(gsrc));
}
__device__ __forceinline__ void cp_commit() {
    asm volatile("cp.async.commit_group;" ::: "memory");
}
__device__ __forceinline__ void cp_wait_all() {
    asm volatile("cp.async.wait_group 0;" ::: "memory");
}

// ---- tensor-core primitives ----
__device__ __forceinline__ void ldsm4(uint32_t* r, uint32_t a) {
    asm volatile("ldmatrix.sync.aligned.m8n8.x4.shared.b16 {%0,%1,%2,%3},[%4];"
                 : "=r"(r[0]), "=r"(r[1]), "=r"(r[2]), "=r"(r[3])
                 : "r"(a));
}
__device__ __forceinline__ void mma16(float* c, const uint32_t* a, uint32_t b0,
                                      uint32_t b1) {
    asm volatile(
        "mma.sync.aligned.m16n8k16.row.col.f32.bf16.bf16.f32 "
        "{%0,%1,%2,%3},{%4,%5,%6,%7},{%8,%9},{%0,%1,%2,%3};"
        : "+f"(c[0]), "+f"(c[1]), "+f"(c[2]), "+f"(c[3])
        : "r"(a[0]), "r"(a[1]), "r"(a[2]), "r"(a[3]), "r"(b0), "r"(b1));
}

// split x,y -> packed bf16 hi pair + lo pair (memory order: low 16 bits first)
__device__ __forceinline__ void split2(float x, float y, uint32_t& hi,
                                       uint32_t& lo) {
    __nv_bfloat16 hx = __float2bfloat16(x), hy = __float2bfloat16(y);
    float rx = x - __bfloat162float(hx), ry = y - __bfloat162float(hy);
    __nv_bfloat16 lx = __float2bfloat16(rx), ly = __float2bfloat16(ry);
    hi = ((uint32_t)__bfloat16_as_ushort(hy) << 16) | __bfloat16_as_ushort(hx);
    lo = ((uint32_t)__bfloat16_as_ushort(ly) << 16) | __bfloat16_as_ushort(lx);
}

// ---- prep: W[(s*C_IN+k)*C_OUT+n] -> W_T hi/lo bf16 images [s][comp][n][PADK]
template <int C_IN, int C_OUT>
__device__ void prep1(const float* __restrict__ W, unsigned short* __restrict__ img,
                      int e) {
    constexpr int PADK = C_IN + 8;
    const int per_s = C_IN * C_OUT;
    const int s = e / per_s, r = e % per_s;
    const int k = r / C_OUT, n = r % C_OUT;
    const float v = W[e];
    __nv_bfloat16 h = __float2bfloat16(v);
    __nv_bfloat16 l = __float2bfloat16(v - __bfloat162float(h));
    img[((size_t)(s * 2 + 0) * C_OUT + n) * PADK + k] = __bfloat16_as_ushort(h);
    img[((size_t)(s * 2 + 1) * C_OUT + n) * PADK + k] = __bfloat16_as_ushort(l);
}

__global__ void prep_kernel(const float* W0, const float* W1, const float* W2) {
    const int t = blockIdx.x * blockDim.x + threadIdx.x;
    const int n0 = SEQ * 32 * 64, n1 = SEQ * 64 * 64, n2 = SEQ * 64 * 32;
    if (t < n0) prep1<32, 64>(W0, g_w0b, t);
    const int t1 = t - n0;
    if (t1 >= 0 && t1 < n1) prep1<64, 64>(W1, g_w1b, t1);
    const int t2 = t1 - n1;
    if (t2 >= 0 && t2 < n2) prep1<64, 32>(W2, g_w2b, t2);
}

// ---- layer kernel: gather -> bf16 split -> 3-product m16n8k16 mma ----
// Uniform work split: each of 8 warps owns an m32 x n32 output block
// (rows (wid&3)*32, cols (wid>>2)*C_OUT/2). All warps stage + compute.
template <int C_IN, int C_OUT, bool ACT>
__global__ __launch_bounds__(256) void spiral_mma(
    const float* __restrict__ h_in, const int* __restrict__ idx,
    const unsigned short* __restrict__ Bimg, const float* __restrict__ bias,
    float* __restrict__ h_out, int n_nodes) {
    constexpr int THREADS = 256, TILE_N = 128;
    constexpr int PADK = C_IN + 8;
    constexpr int ROWB = PADK * 2;            // bytes per smem row
    constexpr int ATILE = TILE_N * ROWB;      // bytes per A component
    constexpr int BTILE = C_OUT * ROWB;       // bytes per B component
    constexpr int NHALF = C_OUT / 2;          // cols per warp
    constexpr int NTW = NHALF / 8;            // n8 tiles per warp
    constexpr int KS = C_IN / 16;             // k16 steps per neighbor
    constexpr int FPT = TILE_N * C_IN / THREADS;  // floats gathered per thread
    constexpr int V4 = FPT / 4;
    constexpr int TPR = C_IN / FPT;           // threads per gathered row (2)

    extern __shared__ char smem[];
    uint32_t sb;
    asm("{ .reg .u64 t; cvta.to.shared.u64 t, %1; cvt.u32.u64 %0, t; }"
        : "=r"(sb) : "l"(smem));
    char* Abase = smem;                  // [2 buf][2 comp][ATILE]
    const uint32_t sbB = sb + 4 * ATILE; // [2 buf][2*BTILE]

    const int tid = threadIdx.x, wid = tid >> 5, lane = tid & 31;
    const int g = lane >> 2, q = lane & 3;
    const int mbase = (wid & 3) * 32;    // warp row base (m32)
    const int nbase = (wid >> 2) * NHALF;  // warp col base (n32 / n16)
    const int nb = blockIdx.x * TILE_N;

    // gather mapping: 2 threads per row
    const int grow = tid / TPR;
    const int goff = (tid % TPR) * FPT;

    // ldmatrix address offsets (within a component tile), two m16 tiles
    const uint32_t aOff0 =
        (uint32_t)(mbase + (lane & 7) + ((lane >> 3) & 1) * 8) * ROWB +
        ((lane >> 4) & 1) * 16;
    const uint32_t aOff1 = aOff0 + 16 * ROWB;
    const uint32_t bOff =
        (uint32_t)(nbase + (lane & 7) + ((lane >> 4) & 1) * 8) * ROWB +
        ((lane >> 3) & 1) * 16;

    auto issueB = [&](int s, int buf) {
        const char* src = (const char*)(Bimg + (size_t)s * 2 * C_OUT * PADK);
        const uint32_t dst = sbB + buf * 2 * BTILE;
        constexpr int CH = 2 * BTILE / 16;
#pragma unroll
        for (int i = tid; i < CH; i += THREADS) cp16(dst + i * 16, src + i * 16);
        cp_commit();
    };

    float4 G[V4];
    auto loadA = [&](int s) {
        const int node = nb + grow;
        const int gi = (node < n_nodes) ? __ldg(&idx[node * SEQ + s]) : 0;
        const float4* src =
            reinterpret_cast<const float4*>(h_in + (size_t)gi * C_IN + goff);
#pragma unroll
        for (int j = 0; j < V4; ++j) G[j] = __ldg(src + j);
    };
    auto storeA = [&](int buf) {
        char* Ah = Abase + buf * 2 * ATILE;
        char* Al = Ah + ATILE;
#pragma unroll
        for (int j = 0; j < V4; ++j) {
            const float4 v = G[j];
            uint32_t h01, l01, h23, l23;
            split2(v.x, v.y, h01, l01);
            split2(v.z, v.w, h23, l23);
            const int off = grow * ROWB + (goff + 4 * j) * 2;
            *reinterpret_cast<uint2*>(Ah + off) = make_uint2(h01, h23);
            *reinterpret_cast<uint2*>(Al + off) = make_uint2(l01, l23);
        }
    };

    issueB(0, 0);
    loadA(0);
    storeA(0);
    loadA(1);

    float acc[2][NTW][4];
#pragma unroll
    for (int t = 0; t < 2; ++t)
#pragma unroll
        for (int nt = 0; nt < NTW; ++nt)
#pragma unroll
            for (int j = 0; j < 4; ++j) acc[t][nt][j] = 0.0f;

#pragma unroll 1
    for (int s = 0; s < SEQ; ++s) {
        const int buf = s & 1;
        cp_wait_all();
        __syncthreads();
        if (s + 1 < SEQ) issueB(s + 1, buf ^ 1);

        const uint32_t Ah = sb + buf * 2 * ATILE;
        const uint32_t Al = Ah + ATILE;
        const uint32_t Bh = sbB + buf * 2 * BTILE;
        const uint32_t Bl = Bh + BTILE;
#pragma unroll
        for (int k = 0; k < KS; ++k) {
            uint32_t ah[2][4], al[2][4];
            ldsm4(ah[0], Ah + aOff0 + k * 32);
            ldsm4(ah[1], Ah + aOff1 + k * 32);
            ldsm4(al[0], Al + aOff0 + k * 32);
            ldsm4(al[1], Al + aOff1 + k * 32);
#pragma unroll
            for (int j = 0; j < NTW / 2; ++j) {
                uint32_t bh[4], bl[4];
                const uint32_t bo = bOff + j * 16 * ROWB + k * 32;
                ldsm4(bh, Bh + bo);
                ldsm4(bl, Bl + bo);
#pragma unroll
                for (int t = 0; t < 2; ++t) {
                    mma16(acc[t][2 * j], ah[t], bh[0], bh[1]);
                    mma16(acc[t][2 * j], al[t], bh[0], bh[1]);
                    mma16(acc[t][2 * j], ah[t], bl[0], bl[1]);
                    mma16(acc[t][2 * j + 1], ah[t], bh[2], bh[3]);
                    mma16(acc[t][2 * j + 1], al[t], bh[2], bh[3]);
                    mma16(acc[t][2 * j + 1], ah[t], bl[2], bl[3]);
                }
            }
        }

        if (s + 1 < SEQ) {
            storeA(buf ^ 1);           // G holds A(s+1)
            if (s + 2 < SEQ) loadA(s + 2);
        }
    }

    // epilogue: bias + optional ELU, 8B stores (each warp: m32 x n32 block)
#pragma unroll
    for (int t = 0; t < 2; ++t) {
        const int r0 = nb + mbase + 16 * t + g;
        const int r1 = r0 + 8;
#pragma unroll
        for (int nt = 0; nt < NTW; ++nt) {
            const int c = nbase + nt * 8 + 2 * q;
            const float bx = __ldg(&bias[c]);
            const float by = __ldg(&bias[c + 1]);
            float v0 = acc[t][nt][0] + bx;
            float v1 = acc[t][nt][1] + by;
            float v2 = acc[t][nt][2] + bx;
            float v3 = acc[t][nt][3] + by;
            if (ACT) {
                v0 = (v0 > 0.0f) ? v0 : expm1f(v0);
                v1 = (v1 > 0.0f) ? v1 : expm1f(v1);
                v2 = (v2 > 0.0f) ? v2 : expm1f(v2);
                v3 = (v3 > 0.0f) ? v3 : expm1f(v3);
            }
            if (r0 < n_nodes)
                *reinterpret_cast<float2*>(h_out + (size_t)r0 * C_OUT + c) =
                    make_float2(v0, v1);
            if (r1 < n_nodes)
                *reinterpret_cast<float2*>(h_out + (size_t)r1 * C_OUT + c) =
                    make_float2(v2, v3);
        }
    }
}

template <int C_IN, int C_OUT>
constexpr int smem_sz() {
    return 4 * 128 * (C_IN + 8) * 2 + 4 * C_OUT * (C_IN + 8) * 2;
}

extern "C" void kernel_launch(void* const* d_in, const int* in_sizes, int n_in,
                              void* d_out, int out_size) {
    const float* x = (const float*)d_in[0];    // [N,32]
    const int* idx = (const int*)d_in[1];      // [N,12]
    const float* W0 = (const float*)d_in[2];
    const float* b0 = (const float*)d_in[3];
    const float* W1 = (const float*)d_in[4];
    const float* b1 = (const float*)d_in[5];
    const float* W2 = (const float*)d_in[6];
    const float* b2 = (const float*)d_in[7];
    float* out = (float*)d_out;

    const int n = in_sizes[0] / 32;
    const int grid = (n + 127) / 128;

    float *h1, *h2;
    unsigned short *w0b, *w1b, *w2b;
    cudaGetSymbolAddress((void**)&h1, g_h1);
    cudaGetSymbolAddress((void**)&h2, g_h2);
    cudaGetSymbolAddress((void**)&w0b, g_w0b);
    cudaGetSymbolAddress((void**)&w1b, g_w1b);
    cudaGetSymbolAddress((void**)&w2b, g_w2b);

    prep_kernel<<<(SEQ * (32 * 64 + 64 * 64 + 64 * 32) + 255) / 256, 256>>>(
        W0, W1, W2);

    constexpr int S0 = smem_sz<32, 64>();   // 61.4 KB
    constexpr int S1 = smem_sz<64, 64>();   // 110.6 KB
    constexpr int S2 = smem_sz<64, 32>();   // 92.2 KB
    cudaFuncSetAttribute(spiral_mma<32, 64, true>,
                         cudaFuncAttributeMaxDynamicSharedMemorySize, S0);
    cudaFuncSetAttribute(spiral_mma<64, 64, true>,
                         cudaFuncAttributeMaxDynamicSharedMemorySize, S1);
    cudaFuncSetAttribute(spiral_mma<64, 32, false>,
                         cudaFuncAttributeMaxDynamicSharedMemorySize, S2);

    spiral_mma<32, 64, true><<<grid, 256, S0>>>(x, idx, w0b, b0, h1, n);
    spiral_mma<64, 64, true><<<grid, 256, S1>>>(h1, idx, w1b, b1, h2, n);
    spiral_mma<64, 32, false><<<grid, 256, S2>>>(h2, idx, w2b, b2, out, n);
}